// round 15
// baseline (speedup 1.0000x reference)
#include <cuda_runtime.h>
#include <cuda_fp16.h>
#include <math.h>
#include <stdint.h>

#define NN 4096      // nodes
#define DIN 768
#define HID 512
#define DOUT 768
#define H 4
#define HCAT (H*HID) // 2048
#define ALPHA 0.2f
#define NEG_BIG -9e15f

// ---------------- scratch (__device__ globals; no allocations) ----------------
__device__ __half g_Xh[(long)NN * DIN];            // fp16 X
__device__ __half g_W0T[(long)H * HID * DIN];      // W0 transposed [h][o][f]
__device__ __half g_rp0T[(long)HCAT * DIN];        // rp0_w transposed
__device__ __half g_W1T[(long)H * DOUT * HCAT];    // W1 transposed
__device__ __half g_rp1T[(long)DOUT * HCAT];       // rp1_w transposed
__device__ __half g_Wh0T[(long)H * HID * NN];      // Wh0 transposed [h][o][n]
__device__ __half g_Wh1T[(long)H * DOUT * NN];     // Wh1 transposed
__device__ __half g_P[(long)H * NN * NN];          // softmax weights fp16 (134 MB)
__device__ __half g_H1[(long)NN * HCAT];           // layer-0 output fp16
__device__ float  g_ssrc[H * NN];
__device__ float  g_sdst[H * NN];
__device__ float  g_Hcat[(long)NN * HCAT];
__device__ float  g_R[(long)NN * HCAT];
__device__ float  g_HP1h[(long)H * NN * DOUT];

// ================= fp16 mma.sync GEMM core (5-stage cp.async, BK=32) =================
#define BM 128
#define BN 128
#define BKH 32                       // halves per stage k-depth
#define NST 5
#define LDH 40                       // padded halves per smem row
#define LDW (LDH/2)                  // u32 stride = 20
#define A_ST (BM * LDH)              // 5120 halves
#define B_ST (BN * LDH)              // 5120 halves
#define STG_H (A_ST + B_ST)          // 10240 halves
#define GEMM_SMEM (NST * STG_H * 2)  // 102400 bytes
#define NYT (NN / BM)                // 32 M-tiles (M=4096 for all GEMMs)
#define LDT 136                      // staged C^T tile row stride (halves)

__device__ __forceinline__ void cp16(uint32_t s, const void* g) {
    asm volatile("cp.async.cg.shared.global [%0], [%1], 16;\n" :: "r"(s), "l"(g));
}

__device__ __forceinline__ void mma_f16(float* d, const uint32_t* a, const uint32_t* b) {
    asm volatile(
        "mma.sync.aligned.m16n8k16.row.col.f32.f16.f16.f32 "
        "{%0,%1,%2,%3}, {%4,%5,%6,%7}, {%8,%9}, {%0,%1,%2,%3};"
        : "+f"(d[0]), "+f"(d[1]), "+f"(d[2]), "+f"(d[3])
        : "r"(a[0]), "r"(a[1]), "r"(a[2]), "r"(a[3]), "r"(b[0]), "r"(b[1]));
}

// C[m][n] = scale * sum_k Abase[m][k] * Bbase[n][k] (+bias[n]); transH: store half C^T.
__device__ __forceinline__ void hgemm_core(
    const __half* __restrict__ Abase, const __half* __restrict__ Bbase,
    void* __restrict__ Cv, long czoff, int K, int ldc,
    float scale, const float* __restrict__ bias, int transH,
    int bm, int bn, __half* smh)
{
    const int tid = threadIdx.x;
    const int w = tid >> 5, lane = tid & 31;
    const int wm = w >> 1, wn = w & 1;       // 4x2 warp grid (warp tile 32x64)
    const int g = lane >> 2, tg = lane & 3;

    float acc[2][8][4];
#pragma unroll
    for (int mi = 0; mi < 2; mi++)
#pragma unroll
        for (int ni = 0; ni < 8; ni++)
#pragma unroll
            for (int q = 0; q < 4; q++) acc[mi][ni][q] = 0.f;

    uint32_t smem_u32;
    asm("{ .reg .u64 t; cvta.to.shared.u64 t, %1; cvt.u32.u64 %0, t; }"
        : "=r"(smem_u32) : "l"(smh));

    int crow[2], ccol[2];
#pragma unroll
    for (int i = 0; i < 2; i++) {
        int c = tid + i * 256;
        crow[i] = c >> 2;             // 0..127
        ccol[i] = (c & 3) * 8;        // half offset 0/8/16/24
    }
    const int nk = K / BKH;

    auto load_stage = [&](int slot, int kt) {
        uint32_t sa = smem_u32 + slot * STG_H * 2;
        uint32_t sb = sa + A_ST * 2;
        long ko = (long)kt * BKH;
#pragma unroll
        for (int i = 0; i < 2; i++) {
            cp16(sa + (crow[i] * LDH + ccol[i]) * 2,
                 Abase + (long)crow[i] * K + ko + ccol[i]);
            cp16(sb + (crow[i] * LDH + ccol[i]) * 2,
                 Bbase + (long)crow[i] * K + ko + ccol[i]);
        }
    };

    load_stage(0, 0); asm volatile("cp.async.commit_group;\n");
    load_stage(1, 1); asm volatile("cp.async.commit_group;\n");
    load_stage(2, 2); asm volatile("cp.async.commit_group;\n");
    load_stage(3, 3); asm volatile("cp.async.commit_group;\n");

    for (int kt = 0; kt < nk; ++kt) {
        if (kt + 3 < nk)      asm volatile("cp.async.wait_group 3;\n");
        else if (kt + 2 < nk) asm volatile("cp.async.wait_group 2;\n");
        else if (kt + 1 < nk) asm volatile("cp.async.wait_group 1;\n");
        else                  asm volatile("cp.async.wait_group 0;\n");
        __syncthreads();

        const uint32_t* As = (const uint32_t*)(smh + (kt % NST) * STG_H);
        const uint32_t* Bs = As + A_ST / 2;

        // ---- full-stage fragment hoist: issue ALL 24 LDS first (batched MLP),
        // then stream all 32 HMMAs with no load->use stalls inside the stage.
        uint32_t afr[2][2][4];     // [k0][mi][q]
        uint32_t bfr[2][8][2];     // [k0][ni][q]
#pragma unroll
        for (int k0 = 0; k0 < 2; k0++) {
#pragma unroll
            for (int mi = 0; mi < 2; mi++) {
                int r = wm * 32 + mi * 16 + g;
                int base = r * LDW + tg + k0 * 8;
                afr[k0][mi][0] = As[base];
                afr[k0][mi][1] = As[base + 8 * LDW];
                afr[k0][mi][2] = As[base + 4];
                afr[k0][mi][3] = As[base + 8 * LDW + 4];
            }
#pragma unroll
            for (int ni = 0; ni < 8; ni++) {
                int n = wn * 64 + ni * 8 + g;
                int base = n * LDW + tg + k0 * 8;
                bfr[k0][ni][0] = Bs[base];
                bfr[k0][ni][1] = Bs[base + 4];
            }
        }
#pragma unroll
        for (int k0 = 0; k0 < 2; k0++)
#pragma unroll
            for (int mi = 0; mi < 2; mi++)
#pragma unroll
                for (int ni = 0; ni < 8; ni++)
                    mma_f16(acc[mi][ni], afr[k0][mi], bfr[k0][ni]);

        if (kt + 4 < nk) load_stage((kt + 4) % NST, kt + 4);
        asm volatile("cp.async.commit_group;\n");
    }

    if (!transH) {
        // direct f32 store: acc[mi][ni] = {(r0,c0),(r0,c0+1),(r0+8,c0),(r0+8,c0+1)}
#pragma unroll
        for (int mi = 0; mi < 2; mi++) {
            int r0 = bm + wm * 32 + mi * 16 + g;
#pragma unroll
            for (int ni = 0; ni < 8; ni++) {
                int c0 = bn + wn * 64 + ni * 8 + 2 * tg;
                float* Cf = (float*)Cv + czoff;
                float b0 = bias ? bias[c0] : 0.f;
                float b1 = bias ? bias[c0 + 1] : 0.f;
                *(float2*)&Cf[(long)r0 * ldc + c0] =
                    make_float2(acc[mi][ni][0] * scale + b0, acc[mi][ni][1] * scale + b1);
                *(float2*)&Cf[(long)(r0 + 8) * ldc + c0] =
                    make_float2(acc[mi][ni][2] * scale + b0, acc[mi][ni][3] * scale + b1);
            }
        }
    } else {
        // staged coalesced transposed store: smem tile st[c][r] (128 x LDT halves)
        __syncthreads();                       // all LDS reads of stage data done
        __half* st = smh;
#pragma unroll
        for (int mi = 0; mi < 2; mi++) {
            int rl0 = wm * 32 + mi * 16 + g;   // local row
#pragma unroll
            for (int ni = 0; ni < 8; ni++) {
                int cl0 = wn * 64 + ni * 8 + 2 * tg;  // local col
                st[cl0 * LDT + rl0]             = __float2half_rn(acc[mi][ni][0] * scale);
                st[(cl0 + 1) * LDT + rl0]       = __float2half_rn(acc[mi][ni][1] * scale);
                st[cl0 * LDT + rl0 + 8]         = __float2half_rn(acc[mi][ni][2] * scale);
                st[(cl0 + 1) * LDT + rl0 + 8]   = __float2half_rn(acc[mi][ni][3] * scale);
            }
        }
        __syncthreads();
        __half* Ch = (__half*)Cv + czoff;
#pragma unroll
        for (int i = 0; i < 8; i++) {
            int chunk = tid + i * 256;         // 2048 float4 chunks
            int row = chunk >> 4;              // 0..127 (c dim)
            int off = (chunk & 15) * 8;        // half offset within row
            float4 v = *(float4*)&st[row * LDT + off];
            *(float4*)&Ch[(long)(bn + row) * NN + bm + off] = v;
        }
    }
}

// single-GEMM wrapper (3D grid: x=N tiles, y=M tiles, z=batch)
__global__ __launch_bounds__(256, 2)
void hgemm_mma(const __half* __restrict__ A, const __half* __restrict__ B, void* Cv,
               int K, long aB, long bB, long cB, int ldc,
               float scale, const float* __restrict__ bias, int transH)
{
    extern __shared__ __half smh[];
    const int bz = blockIdx.z;
    const int bm = blockIdx.y * BM;
    const int bn = blockIdx.x * BN;
    hgemm_core(A + (long)bz * aB + (long)bm * K,
               B + (long)bz * bB + (long)bn * K,
               Cv, (long)bz * cB, K, ldc, scale, bias, transH, bm, bn, smh);
}

// dual-GEMM wrapper: two independent GEMMs sharing A and K, flattened 1D grid.
__global__ __launch_bounds__(256, 2)
void hgemm_dual(const __half* __restrict__ A, int K,
                const __half* __restrict__ B0, void* C0, long bB0, long cB0,
                int ldc0, float sc0, const float* __restrict__ bias0, int tH0,
                int nx0, int nt0,
                const __half* __restrict__ B1, void* C1, long bB1, long cB1,
                int ldc1, float sc1, const float* __restrict__ bias1, int tH1,
                int nx1)
{
    extern __shared__ __half smh[];
    int t = blockIdx.x;
    const __half* B; void* C; long bB, cB; int ldc, tH, nx; float sc; const float* bias;
    if (t < nt0) { B = B0; C = C0; bB = bB0; cB = cB0; ldc = ldc0; sc = sc0; bias = bias0; tH = tH0; nx = nx0; }
    else { t -= nt0; B = B1; C = C1; bB = bB1; cB = cB1; ldc = ldc1; sc = sc1; bias = bias1; tH = tH1; nx = nx1; }
    int z = t / (nx * NYT);
    int rem = t % (nx * NYT);
    int y = rem / nx, x = rem % nx;
    int bm = y * BM, bn = x * BN;
    hgemm_core(A + (long)bm * K,
               B + (long)z * bB + (long)bn * K,
               C, (long)z * cB, K, ldc, sc, bias, tH, bm, bn, smh);
}

// ---------------- batched transpose pair f32 -> fp16 ----------------
__global__ void transpose2(const float* __restrict__ in0, __half* __restrict__ out0,
                           int C0, int nz0,
                           const float* __restrict__ in1, __half* __restrict__ out1,
                           int C1, int R)
{
    __shared__ float t[32][33];
    int z = blockIdx.z;
    const float* in; __half* out; int C;
    if (z < nz0) { in = in0 + (long)z * R * C0; out = out0 + (long)z * R * C0; C = C0; }
    else         { in = in1; out = out1; C = C1; }
    int c0 = blockIdx.x * 32, r0 = blockIdx.y * 32;
    if (c0 >= C) return;
    int tx = threadIdx.x, ty = threadIdx.y;
#pragma unroll
    for (int i = 0; i < 4; i++)
        t[ty + i * 8][tx] = in[(long)(r0 + ty + i * 8) * C + c0 + tx];
    __syncthreads();
#pragma unroll
    for (int i = 0; i < 4; i++)
        out[(long)(c0 + ty + i * 8) * R + r0 + tx] = __float2half_rn(t[tx][ty + i * 8]);
}

// ---------------- f32 -> fp16 convert ----------------
__global__ void conv_half(const float* __restrict__ in, __half* __restrict__ out, long n)
{
    long i = ((long)blockIdx.x * 256 + threadIdx.x) * 4;
    if (i >= n) return;
    float4 v = *(const float4*)(in + i);
    *(__half2*)(out + i)     = __floats2half2_rn(v.x, v.y);
    *(__half2*)(out + i + 2) = __floats2half2_rn(v.z, v.w);
}

// ---------------- scores from WhT: s[n] = sum_o WhT[h][o][n] * a[o] ----------------
__global__ __launch_bounds__(256)
void scores_kernel(const __half* __restrict__ WhT, const float* __restrict__ a,
                   float* __restrict__ ssrc, float* __restrict__ sdst, int O)
{
    int n = blockIdx.x * 256 + threadIdx.x;
    int h = blockIdx.y;
    const __half* base = WhT + (long)h * O * NN + n;
    const float* a1 = a + (long)h * 2 * O;
    const float* a2 = a1 + O;
    float s1 = 0.f, s2 = 0.f;
#pragma unroll 4
    for (int o = 0; o < O; o++) {
        float v = __half2float(base[(long)o * NN]);
        s1 += v * a1[o];
        s2 += v * a2[o];
    }
    ssrc[h * NN + n] = s1;
    sdst[h * NN + n] = s2;
}

// ---------------- fused 4-head attention row softmax -> P (fp16) ----------------
__global__ __launch_bounds__(256)
void attn4_kernel(const int* __restrict__ adj, const float* __restrict__ ew,
                  const float* __restrict__ ssrc, const float* __restrict__ sdst,
                  __half* __restrict__ P)
{
    extern __shared__ float sl[];            // H * NN floats
    __shared__ float red[H][8];
    const int i = blockIdx.x;
    const int tid = threadIdx.x;
    const long rowbase = (long)i * NN;

    float si[H];
#pragma unroll
    for (int h = 0; h < H; h++) si[h] = ssrc[h * NN + i];

    float lmax[H];
#pragma unroll
    for (int h = 0; h < H; h++) lmax[h] = -INFINITY;

    for (int jb = tid * 4; jb < NN; jb += 1024) {
        int4   am4 = *(const int4*)(adj + rowbase + jb);
        float4 wv4 = *(const float4*)(ew + rowbase + jb);
        int am[4] = {am4.x, am4.y, am4.z, am4.w};
        float wv[4] = {wv4.x, wv4.y, wv4.z, wv4.w};
        bool msk[4];
#pragma unroll
        for (int q = 0; q < 4; q++) msk[q] = (am[q] > 0) || (jb + q == i);
#pragma unroll
        for (int h = 0; h < H; h++) {
            float4 sd4 = *(const float4*)(sdst + (long)h * NN + jb);
            float sdv[4] = {sd4.x, sd4.y, sd4.z, sd4.w};
            float lv[4];
#pragma unroll
            for (int q = 0; q < 4; q++) {
                float x = si[h] + sdv[q];
                float lr = x > 0.f ? x : ALPHA * x;
                float l = (msk[q] ? lr : NEG_BIG) * wv[q];
                lv[q] = l;
                lmax[h] = fmaxf(lmax[h], l);
            }
            *(float4*)&sl[h * NN + jb] = make_float4(lv[0], lv[1], lv[2], lv[3]);
        }
    }
#pragma unroll
    for (int h = 0; h < H; h++) {
        float v = lmax[h];
#pragma unroll
        for (int off = 16; off > 0; off >>= 1) v = fmaxf(v, __shfl_xor_sync(0xffffffffu, v, off));
        if ((tid & 31) == 0) red[h][tid >> 5] = v;
    }
    __syncthreads();
    if (tid < 8) {
#pragma unroll
        for (int h = 0; h < H; h++) {
            float v = red[h][tid];
#pragma unroll
            for (int off = 4; off > 0; off >>= 1) v = fmaxf(v, __shfl_xor_sync(0xffu, v, off));
            if (tid == 0) red[h][0] = v;
        }
    }
    __syncthreads();
    float rowmax[H];
#pragma unroll
    for (int h = 0; h < H; h++) rowmax[h] = red[h][0];
    __syncthreads();

    float lsum[H];
#pragma unroll
    for (int h = 0; h < H; h++) lsum[h] = 0.f;
    for (int j = tid; j < NN; j += 256) {
#pragma unroll
        for (int h = 0; h < H; h++) {
            float e = __expf(sl[h * NN + j] - rowmax[h]);
            sl[h * NN + j] = e;
            lsum[h] += e;
        }
    }
#pragma unroll
    for (int h = 0; h < H; h++) {
        float v = lsum[h];
#pragma unroll
        for (int off = 16; off > 0; off >>= 1) v += __shfl_xor_sync(0xffffffffu, v, off);
        if ((tid & 31) == 0) red[h][tid >> 5] = v;
    }
    __syncthreads();
    if (tid < 8) {
#pragma unroll
        for (int h = 0; h < H; h++) {
            float v = red[h][tid];
#pragma unroll
            for (int off = 4; off > 0; off >>= 1) v += __shfl_xor_sync(0xffu, v, off);
            if (tid == 0) red[h][0] = v;
        }
    }
    __syncthreads();
    float inv[H];
#pragma unroll
    for (int h = 0; h < H; h++) inv[h] = 1.f / red[h][0];

#pragma unroll
    for (int h = 0; h < H; h++) {
        __half* prow = P + ((long)h * NN + i) * NN;
        const float* slh = sl + h * NN;
        for (int jb = tid * 4; jb < NN; jb += 1024) {
            __half2 h0 = __floats2half2_rn(slh[jb] * inv[h], slh[jb + 1] * inv[h]);
            __half2 h1 = __floats2half2_rn(slh[jb + 2] * inv[h], slh[jb + 3] * inv[h]);
            *(__half2*)(prow + jb) = h0;
            *(__half2*)(prow + jb + 2) = h1;
        }
    }
}
#define ATTN_SMEM (H * NN * 4)

// ---------------- layer-0 epilogue: H1 = elu(LN(elu(Hcat)+R)) -> fp16 ----------------
__global__ __launch_bounds__(256)
void fuse0_kernel(const float* __restrict__ Hcat, const float* __restrict__ R,
                  const float* __restrict__ g, const float* __restrict__ b,
                  __half* __restrict__ H1)
{
    __shared__ float red[8];
    const int n = blockIdx.x;
    const int tid = threadIdx.x;
    float v[8];
    float sum = 0.f;
#pragma unroll
    for (int t = 0; t < 8; t++) {
        int c = tid + t * 256;
        float x = Hcat[(long)n * HCAT + c];
        x = x > 0.f ? x : (expf(x) - 1.f);
        x += R[(long)n * HCAT + c];
        v[t] = x;
        sum += x;
    }
#pragma unroll
    for (int off = 16; off > 0; off >>= 1) sum += __shfl_xor_sync(0xffffffffu, sum, off);
    if ((tid & 31) == 0) red[tid >> 5] = sum;
    __syncthreads();
    if (tid < 8) {
        float x = red[tid];
#pragma unroll
        for (int off = 4; off > 0; off >>= 1) x += __shfl_xor_sync(0xffu, x, off);
        if (tid == 0) red[0] = x;
    }
    __syncthreads();
    const float mean = red[0] / HCAT;
    __syncthreads();
    float vs = 0.f;
#pragma unroll
    for (int t = 0; t < 8; t++) { float d = v[t] - mean; vs += d * d; }
#pragma unroll
    for (int off = 16; off > 0; off >>= 1) vs += __shfl_xor_sync(0xffffffffu, vs, off);
    if ((tid & 31) == 0) red[tid >> 5] = vs;
    __syncthreads();
    if (tid < 8) {
        float x = red[tid];
#pragma unroll
        for (int off = 4; off > 0; off >>= 1) x += __shfl_xor_sync(0xffu, x, off);
        if (tid == 0) red[0] = x;
    }
    __syncthreads();
    const float rstd = rsqrtf(red[0] / HCAT + 1e-5f);
#pragma unroll
    for (int t = 0; t < 8; t++) {
        int c = tid + t * 256;
        float y = (v[t] - mean) * rstd * g[c] + b[c];
        y = y > 0.f ? y : (expf(y) - 1.f);
        H1[(long)n * HCAT + c] = __float2half_rn(y);
    }
}

// ---------------- final: out = LN(sum_h HP1h + R1) ----------------
__global__ __launch_bounds__(256)
void final_kernel(const float* __restrict__ HP1h, const float* __restrict__ R,
                  const float* __restrict__ g, const float* __restrict__ b,
                  float* __restrict__ out)
{
    __shared__ float red[8];
    const int n = blockIdx.x;
    const int tid = threadIdx.x;
    float v[3];
    float sum = 0.f;
#pragma unroll
    for (int t = 0; t < 3; t++) {
        int c = tid + t * 256;
        long off = (long)n * DOUT + c;
        float x = R[off];
#pragma unroll
        for (int h = 0; h < H; h++)
            x += HP1h[(long)h * NN * DOUT + off];
        v[t] = x;
        sum += x;
    }
#pragma unroll
    for (int off = 16; off > 0; off >>= 1) sum += __shfl_xor_sync(0xffffffffu, sum, off);
    if ((tid & 31) == 0) red[tid >> 5] = sum;
    __syncthreads();
    if (tid < 8) {
        float x = red[tid];
#pragma unroll
        for (int off = 4; off > 0; off >>= 1) x += __shfl_xor_sync(0xffu, x, off);
        if (tid == 0) red[0] = x;
    }
    __syncthreads();
    const float mean = red[0] / DOUT;
    __syncthreads();
    float vs = 0.f;
#pragma unroll
    for (int t = 0; t < 3; t++) { float d = v[t] - mean; vs += d * d; }
#pragma unroll
    for (int off = 16; off > 0; off >>= 1) vs += __shfl_xor_sync(0xffffffffu, vs, off);
    if ((tid & 31) == 0) red[tid >> 5] = vs;
    __syncthreads();
    if (tid < 8) {
        float x = red[tid];
#pragma unroll
        for (int off = 4; off > 0; off >>= 1) x += __shfl_xor_sync(0xffu, x, off);
        if (tid == 0) red[0] = x;
    }
    __syncthreads();
    const float rstd = rsqrtf(red[0] / DOUT + 1e-5f);
#pragma unroll
    for (int t = 0; t < 3; t++) {
        int c = tid + t * 256;
        out[(long)n * DOUT + c] = (v[t] - mean) * rstd * g[c] + b[c];
    }
}

// ---------------- host ----------------
extern "C" void kernel_launch(void* const* d_in, const int* in_sizes, int n_in,
                              void* d_out, int out_size)
{
    const float* X    = (const float*)d_in[0];
    const int*   adj  = (const int*)  d_in[1];
    const float* ew   = (const float*)d_in[2];
    const float* W0   = (const float*)d_in[3];
    const float* a0   = (const float*)d_in[4];
    const float* W1   = (const float*)d_in[5];
    const float* a1   = (const float*)d_in[6];
    const float* rp0w = (const float*)d_in[7];
    const float* rp0b = (const float*)d_in[8];
    const float* rp1w = (const float*)d_in[9];
    const float* rp1b = (const float*)d_in[10];
    const float* ln0g = (const float*)d_in[11];
    const float* ln0b = (const float*)d_in[12];
    const float* ln1g = (const float*)d_in[13];
    const float* ln1b = (const float*)d_in[14];
    float* out = (float*)d_out;

    __half *Xh, *W0T, *rp0T, *W1T, *rp1T, *Wh0T, *Wh1T, *P, *H1;
    float *ssrc, *sdst, *Hcat, *R, *HP1h;
    cudaGetSymbolAddress((void**)&Xh,   g_Xh);
    cudaGetSymbolAddress((void**)&W0T,  g_W0T);
    cudaGetSymbolAddress((void**)&rp0T, g_rp0T);
    cudaGetSymbolAddress((void**)&W1T,  g_W1T);
    cudaGetSymbolAddress((void**)&rp1T, g_rp1T);
    cudaGetSymbolAddress((void**)&Wh0T, g_Wh0T);
    cudaGetSymbolAddress((void**)&Wh1T, g_Wh1T);
    cudaGetSymbolAddress((void**)&P,    g_P);
    cudaGetSymbolAddress((void**)&H1,   g_H1);
    cudaGetSymbolAddress((void**)&ssrc, g_ssrc);
    cudaGetSymbolAddress((void**)&sdst, g_sdst);
    cudaGetSymbolAddress((void**)&Hcat, g_Hcat);
    cudaGetSymbolAddress((void**)&R,    g_R);
    cudaGetSymbolAddress((void**)&HP1h, g_HP1h);

    cudaFuncSetAttribute(hgemm_mma, cudaFuncAttributeMaxDynamicSharedMemorySize, GEMM_SMEM);
    cudaFuncSetAttribute(hgemm_dual, cudaFuncAttributeMaxDynamicSharedMemorySize, GEMM_SMEM);
    cudaFuncSetAttribute(attn4_kernel, cudaFuncAttributeMaxDynamicSharedMemorySize, ATTN_SMEM);

    dim3 blk(256);
    dim3 tb(32, 8);

    // ---- prep (launch #4 is hgemm_dual, for ncu visibility) ----
    transpose2<<<dim3(HCAT/32, DIN/32, H + 1), tb>>>(W0, W0T, HID, H, rp0w, rp0T, HCAT, DIN);
    transpose2<<<dim3(DOUT/32, HCAT/32, H + 1), tb>>>(W1, W1T, DOUT, H, rp1w, rp1T, DOUT, HCAT);
    { long n = (long)NN * DIN; conv_half<<<(unsigned)((n/4 + 255)/256), blk>>>(X, Xh, n); }

    // ===== Layer 0 =====
    // Fused: Wh0T[h] = (Xh @ W0[h])^T  AND  R = Xh @ rp0w + rp0b  (both K=768)
    {
        int nx0 = HID / BN;                  // 4
        int nt0 = nx0 * NYT * H;             // 512
        int nx1 = HCAT / BN;                 // 16
        hgemm_dual<<<nt0 + nx1 * NYT, blk, GEMM_SMEM>>>(
            Xh, DIN,
            W0T, Wh0T, (long)HID * DIN, (long)HID * NN, NN, 1.f, nullptr, 1, nx0, nt0,
            rp0T, R, 0L, 0L, HCAT, 1.f, rp0b, 0, nx1);
    }
    scores_kernel<<<dim3(NN/256, H), blk>>>(Wh0T, a0, ssrc, sdst, HID);
    attn4_kernel<<<NN, blk, ATTN_SMEM>>>(adj, ew, ssrc, sdst, P);
    // Hcat[n][h*512+o] = P[h] @ Wh0[h] : N=512 K=4096, f32 store ldc=2048
    hgemm_mma<<<dim3(HID/BN, NN/BM, H), blk, GEMM_SMEM>>>(
        P, Wh0T, Hcat, NN, (long)NN * NN, (long)HID * NN, (long)HID, HCAT,
        1.f, nullptr, 0);
    fuse0_kernel<<<NN, blk>>>(Hcat, R, ln0g, ln0b, H1);

    // ===== Layer 1 =====
    // Fused: Wh1T[h] = (H1 @ W1[h])^T  AND  R1 = H1 @ rp1w + rp1b  (both K=2048)
    {
        int nx0 = DOUT / BN;                 // 6
        int nt0 = nx0 * NYT * H;             // 768
        int nx1 = DOUT / BN;                 // 6
        hgemm_dual<<<nt0 + nx1 * NYT, blk, GEMM_SMEM>>>(
            H1, HCAT,
            W1T, Wh1T, (long)DOUT * HCAT, (long)DOUT * NN, NN, 1.f, nullptr, 1, nx0, nt0,
            rp1T, R, 0L, 0L, DOUT, 1.f, rp1b, 0, nx1);
    }
    scores_kernel<<<dim3(NN/256, H), blk>>>(Wh1T, a1, ssrc, sdst, DOUT);
    attn4_kernel<<<NN, blk, ATTN_SMEM>>>(adj, ew, ssrc, sdst, P);
    // HP1h[h] = 0.25 * P[h] @ Wh1[h] : N=768 K=4096, f32 store
    hgemm_mma<<<dim3(DOUT/BN, NN/BM, H), blk, GEMM_SMEM>>>(
        P, Wh1T, HP1h, NN, (long)NN * NN, (long)DOUT * NN, (long)NN * DOUT, DOUT,
        0.25f, nullptr, 0);
    final_kernel<<<NN, blk>>>(HP1h, R, ln1g, ln1b, out);
}

// round 16
// speedup vs baseline: 1.0822x; 1.0822x over previous
#include <cuda_runtime.h>
#include <cuda_fp16.h>
#include <math.h>
#include <stdint.h>

#define NN 4096      // nodes
#define DIN 768
#define HID 512
#define DOUT 768
#define H 4
#define HCAT (H*HID) // 2048
#define ALPHA 0.2f
#define NEG_BIG -9e15f

// ---------------- scratch (__device__ globals; no allocations) ----------------
__device__ __half g_Xh[(long)NN * DIN];            // fp16 X
__device__ __half g_W0T[(long)H * HID * DIN];      // W0 transposed [h][o][f]
__device__ __half g_rp0T[(long)HCAT * DIN];        // rp0_w transposed
__device__ __half g_W1T[(long)H * DOUT * HCAT];    // W1 transposed
__device__ __half g_rp1T[(long)DOUT * HCAT];       // rp1_w transposed
__device__ __half g_Wh0T[(long)H * HID * NN];      // Wh0 transposed [h][o][n]
__device__ __half g_Wh1T[(long)H * DOUT * NN];     // Wh1 transposed
__device__ __half g_P[(long)H * NN * NN];          // softmax weights fp16 (134 MB)
__device__ __half g_H1[(long)NN * HCAT];           // layer-0 output fp16
__device__ float  g_ssrc[H * NN];
__device__ float  g_sdst[H * NN];
__device__ float  g_Hcat[(long)NN * HCAT];
__device__ float  g_R[(long)NN * HCAT];
__device__ float  g_HP1h[(long)H * NN * DOUT];

// ================= fp16 mma.sync GEMM core (5-stage cp.async + ldmatrix) =================
#define BM 128
#define BN 128
#define BKH 32                       // halves per stage k-depth
#define NST 5
#define LDH 40                       // padded halves per smem row (80 B)
#define LDW (LDH/2)                  // u32 stride = 20
#define A_ST (BM * LDH)              // 5120 halves
#define B_ST (BN * LDH)              // 5120 halves
#define STG_H (A_ST + B_ST)          // 10240 halves
#define GEMM_SMEM (NST * STG_H * 2)  // 102400 bytes
#define NYT (NN / BM)                // 32 M-tiles (M=4096 for all GEMMs)
#define LDT 136                      // staged C^T tile row stride (halves)

__device__ __forceinline__ void cp16(uint32_t s, const void* g) {
    asm volatile("cp.async.cg.shared.global [%0], [%1], 16;\n" :: "r"(s), "l"(g));
}

__device__ __forceinline__ void ldsm4(uint32_t& r0, uint32_t& r1, uint32_t& r2, uint32_t& r3,
                                      uint32_t addr) {
    asm volatile("ldmatrix.sync.aligned.m8n8.x4.shared.b16 {%0,%1,%2,%3}, [%4];"
                 : "=r"(r0), "=r"(r1), "=r"(r2), "=r"(r3) : "r"(addr));
}

__device__ __forceinline__ void mma_f16(float* d, const uint32_t* a, const uint32_t* b) {
    asm volatile(
        "mma.sync.aligned.m16n8k16.row.col.f32.f16.f16.f32 "
        "{%0,%1,%2,%3}, {%4,%5,%6,%7}, {%8,%9}, {%0,%1,%2,%3};"
        : "+f"(d[0]), "+f"(d[1]), "+f"(d[2]), "+f"(d[3])
        : "r"(a[0]), "r"(a[1]), "r"(a[2]), "r"(a[3]), "r"(b[0]), "r"(b[1]));
}

// C[m][n] = scale * sum_k Abase[m][k] * Bbase[n][k] (+bias[n]); transH: store half C^T.
__device__ __forceinline__ void hgemm_core(
    const __half* __restrict__ Abase, const __half* __restrict__ Bbase,
    void* __restrict__ Cv, long czoff, int K, int ldc,
    float scale, const float* __restrict__ bias, int transH,
    int bm, int bn, __half* smh)
{
    const int tid = threadIdx.x;
    const int w = tid >> 5, lane = tid & 31;
    const int wm = w >> 1, wn = w & 1;       // 4x2 warp grid (warp tile 32x64)
    const int g = lane >> 2, tg = lane & 3;

    float acc[2][8][4];
#pragma unroll
    for (int mi = 0; mi < 2; mi++)
#pragma unroll
        for (int ni = 0; ni < 8; ni++)
#pragma unroll
            for (int q = 0; q < 4; q++) acc[mi][ni][q] = 0.f;

    uint32_t smem_u32;
    asm("{ .reg .u64 t; cvta.to.shared.u64 t, %1; cvt.u32.u64 %0, t; }"
        : "=r"(smem_u32) : "l"(smh));

    int crow[2], ccol[2];
#pragma unroll
    for (int i = 0; i < 2; i++) {
        int c = tid + i * 256;
        crow[i] = c >> 2;             // 0..127
        ccol[i] = (c & 3) * 8;        // half offset 0/8/16/24
    }
    const int nk = K / BKH;

    // ldmatrix per-thread base addresses (within a stage)
    // A x4 tiles: t0 r0-7/k0-7, t1 r8-15/k0-7, t2 r0-7/k8-15, t3 r8-15/k8-15
    const uint32_t a_lm = smem_u32 +
        2 * ((wm * 32 + (lane & 7) + ((lane >> 3) & 1) * 8) * LDH + ((lane >> 4) & 1) * 8);
    // B x4 tiles: t0 n0-7/k0-7, t1 n0-7/k8-15, t2 n8-15/k0-7, t3 n8-15/k8-15
    const uint32_t b_lm = smem_u32 + A_ST * 2 +
        2 * ((wn * 64 + (lane & 7) + ((lane >> 4) & 1) * 8) * LDH + ((lane >> 3) & 1) * 8);

    auto load_stage = [&](int slot, int kt) {
        uint32_t sa = smem_u32 + slot * STG_H * 2;
        uint32_t sb = sa + A_ST * 2;
        long ko = (long)kt * BKH;
#pragma unroll
        for (int i = 0; i < 2; i++) {
            cp16(sa + (crow[i] * LDH + ccol[i]) * 2,
                 Abase + (long)crow[i] * K + ko + ccol[i]);
            cp16(sb + (crow[i] * LDH + ccol[i]) * 2,
                 Bbase + (long)crow[i] * K + ko + ccol[i]);
        }
    };

    load_stage(0, 0); asm volatile("cp.async.commit_group;\n");
    load_stage(1, 1); asm volatile("cp.async.commit_group;\n");
    load_stage(2, 2); asm volatile("cp.async.commit_group;\n");
    load_stage(3, 3); asm volatile("cp.async.commit_group;\n");

    for (int kt = 0; kt < nk; ++kt) {
        if (kt + 3 < nk)      asm volatile("cp.async.wait_group 3;\n");
        else if (kt + 2 < nk) asm volatile("cp.async.wait_group 2;\n");
        else if (kt + 1 < nk) asm volatile("cp.async.wait_group 1;\n");
        else                  asm volatile("cp.async.wait_group 0;\n");
        __syncthreads();

        const uint32_t stg = (kt % NST) * STG_H * 2;

        // hoisted fragment batch via ldmatrix: 12 LDSM.x4, then 32 HMMAs
        uint32_t afr[2][2][4];     // [k0][mi][q]
        uint32_t bfr[2][8][2];     // [k0][ni][q]
#pragma unroll
        for (int k0 = 0; k0 < 2; k0++) {
#pragma unroll
            for (int mi = 0; mi < 2; mi++)
                ldsm4(afr[k0][mi][0], afr[k0][mi][1], afr[k0][mi][2], afr[k0][mi][3],
                      a_lm + stg + mi * (16 * LDH * 2) + k0 * 32);
#pragma unroll
            for (int nb = 0; nb < 4; nb++) {
                uint32_t r0, r1, r2, r3;
                ldsm4(r0, r1, r2, r3, b_lm + stg + nb * (16 * LDH * 2) + k0 * 32);
                bfr[k0][2 * nb][0] = r0;     bfr[k0][2 * nb][1] = r1;
                bfr[k0][2 * nb + 1][0] = r2; bfr[k0][2 * nb + 1][1] = r3;
            }
        }
#pragma unroll
        for (int k0 = 0; k0 < 2; k0++)
#pragma unroll
            for (int mi = 0; mi < 2; mi++)
#pragma unroll
                for (int ni = 0; ni < 8; ni++)
                    mma_f16(acc[mi][ni], afr[k0][mi], bfr[k0][ni]);

        if (kt + 4 < nk) load_stage((kt + 4) % NST, kt + 4);
        asm volatile("cp.async.commit_group;\n");
    }

    if (!transH) {
        // direct f32 store: acc[mi][ni] = {(r0,c0),(r0,c0+1),(r0+8,c0),(r0+8,c0+1)}
#pragma unroll
        for (int mi = 0; mi < 2; mi++) {
            int r0 = bm + wm * 32 + mi * 16 + g;
#pragma unroll
            for (int ni = 0; ni < 8; ni++) {
                int c0 = bn + wn * 64 + ni * 8 + 2 * tg;
                float* Cf = (float*)Cv + czoff;
                float b0 = bias ? bias[c0] : 0.f;
                float b1 = bias ? bias[c0 + 1] : 0.f;
                *(float2*)&Cf[(long)r0 * ldc + c0] =
                    make_float2(acc[mi][ni][0] * scale + b0, acc[mi][ni][1] * scale + b1);
                *(float2*)&Cf[(long)(r0 + 8) * ldc + c0] =
                    make_float2(acc[mi][ni][2] * scale + b0, acc[mi][ni][3] * scale + b1);
            }
        }
    } else {
        // staged coalesced transposed store: smem tile st[c][r] (128 x LDT halves)
        __syncthreads();                       // all smem reads of stage data done
        __half* st = smh;
#pragma unroll
        for (int mi = 0; mi < 2; mi++) {
            int rl0 = wm * 32 + mi * 16 + g;   // local row
#pragma unroll
            for (int ni = 0; ni < 8; ni++) {
                int cl0 = wn * 64 + ni * 8 + 2 * tg;  // local col
                st[cl0 * LDT + rl0]             = __float2half_rn(acc[mi][ni][0] * scale);
                st[(cl0 + 1) * LDT + rl0]       = __float2half_rn(acc[mi][ni][1] * scale);
                st[cl0 * LDT + rl0 + 8]         = __float2half_rn(acc[mi][ni][2] * scale);
                st[(cl0 + 1) * LDT + rl0 + 8]   = __float2half_rn(acc[mi][ni][3] * scale);
            }
        }
        __syncthreads();
        __half* Ch = (__half*)Cv + czoff;
#pragma unroll
        for (int i = 0; i < 8; i++) {
            int chunk = tid + i * 256;         // 2048 float4 chunks
            int row = chunk >> 4;              // 0..127 (c dim)
            int off = (chunk & 15) * 8;        // half offset within row
            float4 v = *(float4*)&st[row * LDT + off];
            *(float4*)&Ch[(long)(bn + row) * NN + bm + off] = v;
        }
    }
}

// single-GEMM wrapper (3D grid: x=N tiles, y=M tiles, z=batch)
__global__ __launch_bounds__(256, 2)
void hgemm_mma(const __half* __restrict__ A, const __half* __restrict__ B, void* Cv,
               int K, long aB, long bB, long cB, int ldc,
               float scale, const float* __restrict__ bias, int transH)
{
    extern __shared__ __half smh[];
    const int bz = blockIdx.z;
    const int bm = blockIdx.y * BM;
    const int bn = blockIdx.x * BN;
    hgemm_core(A + (long)bz * aB + (long)bm * K,
               B + (long)bz * bB + (long)bn * K,
               Cv, (long)bz * cB, K, ldc, scale, bias, transH, bm, bn, smh);
}

// dual-GEMM wrapper: two independent GEMMs sharing A and K, flattened 1D grid.
__global__ __launch_bounds__(256, 2)
void hgemm_dual(const __half* __restrict__ A, int K,
                const __half* __restrict__ B0, void* C0, long bB0, long cB0,
                int ldc0, float sc0, const float* __restrict__ bias0, int tH0,
                int nx0, int nt0,
                const __half* __restrict__ B1, void* C1, long bB1, long cB1,
                int ldc1, float sc1, const float* __restrict__ bias1, int tH1,
                int nx1)
{
    extern __shared__ __half smh[];
    int t = blockIdx.x;
    const __half* B; void* C; long bB, cB; int ldc, tH, nx; float sc; const float* bias;
    if (t < nt0) { B = B0; C = C0; bB = bB0; cB = cB0; ldc = ldc0; sc = sc0; bias = bias0; tH = tH0; nx = nx0; }
    else { t -= nt0; B = B1; C = C1; bB = bB1; cB = cB1; ldc = ldc1; sc = sc1; bias = bias1; tH = tH1; nx = nx1; }
    int z = t / (nx * NYT);
    int rem = t % (nx * NYT);
    int y = rem / nx, x = rem % nx;
    int bm = y * BM, bn = x * BN;
    hgemm_core(A + (long)bm * K,
               B + (long)z * bB + (long)bn * K,
               C, (long)z * cB, K, ldc, sc, bias, tH, bm, bn, smh);
}

// ---------------- batched transpose pair f32 -> fp16 ----------------
__global__ void transpose2(const float* __restrict__ in0, __half* __restrict__ out0,
                           int C0, int nz0,
                           const float* __restrict__ in1, __half* __restrict__ out1,
                           int C1, int R)
{
    __shared__ float t[32][33];
    int z = blockIdx.z;
    const float* in; __half* out; int C;
    if (z < nz0) { in = in0 + (long)z * R * C0; out = out0 + (long)z * R * C0; C = C0; }
    else         { in = in1; out = out1; C = C1; }
    int c0 = blockIdx.x * 32, r0 = blockIdx.y * 32;
    if (c0 >= C) return;
    int tx = threadIdx.x, ty = threadIdx.y;
#pragma unroll
    for (int i = 0; i < 4; i++)
        t[ty + i * 8][tx] = in[(long)(r0 + ty + i * 8) * C + c0 + tx];
    __syncthreads();
#pragma unroll
    for (int i = 0; i < 4; i++)
        out[(long)(c0 + ty + i * 8) * R + r0 + tx] = __float2half_rn(t[tx][ty + i * 8]);
}

// ---------------- f32 -> fp16 convert ----------------
__global__ void conv_half(const float* __restrict__ in, __half* __restrict__ out, long n)
{
    long i = ((long)blockIdx.x * 256 + threadIdx.x) * 4;
    if (i >= n) return;
    float4 v = *(const float4*)(in + i);
    *(__half2*)(out + i)     = __floats2half2_rn(v.x, v.y);
    *(__half2*)(out + i + 2) = __floats2half2_rn(v.z, v.w);
}

// ---------------- scores from WhT: s[n] = sum_o WhT[h][o][n] * a[o] ----------------
__global__ __launch_bounds__(256)
void scores_kernel(const __half* __restrict__ WhT, const float* __restrict__ a,
                   float* __restrict__ ssrc, float* __restrict__ sdst, int O)
{
    int n = blockIdx.x * 256 + threadIdx.x;
    int h = blockIdx.y;
    const __half* base = WhT + (long)h * O * NN + n;
    const float* a1 = a + (long)h * 2 * O;
    const float* a2 = a1 + O;
    float s1 = 0.f, s2 = 0.f;
#pragma unroll 4
    for (int o = 0; o < O; o++) {
        float v = __half2float(base[(long)o * NN]);
        s1 += v * a1[o];
        s2 += v * a2[o];
    }
    ssrc[h * NN + n] = s1;
    sdst[h * NN + n] = s2;
}

// ---------------- fused 4-head attention row softmax -> P (fp16) ----------------
__global__ __launch_bounds__(256)
void attn4_kernel(const int* __restrict__ adj, const float* __restrict__ ew,
                  const float* __restrict__ ssrc, const float* __restrict__ sdst,
                  __half* __restrict__ P)
{
    extern __shared__ float sl[];            // H * NN floats
    __shared__ float red[H][8];
    const int i = blockIdx.x;
    const int tid = threadIdx.x;
    const long rowbase = (long)i * NN;

    float si[H];
#pragma unroll
    for (int h = 0; h < H; h++) si[h] = ssrc[h * NN + i];

    float lmax[H];
#pragma unroll
    for (int h = 0; h < H; h++) lmax[h] = -INFINITY;

    for (int jb = tid * 4; jb < NN; jb += 1024) {
        int4   am4 = *(const int4*)(adj + rowbase + jb);
        float4 wv4 = *(const float4*)(ew + rowbase + jb);
        int am[4] = {am4.x, am4.y, am4.z, am4.w};
        float wv[4] = {wv4.x, wv4.y, wv4.z, wv4.w};
        bool msk[4];
#pragma unroll
        for (int q = 0; q < 4; q++) msk[q] = (am[q] > 0) || (jb + q == i);
#pragma unroll
        for (int h = 0; h < H; h++) {
            float4 sd4 = *(const float4*)(sdst + (long)h * NN + jb);
            float sdv[4] = {sd4.x, sd4.y, sd4.z, sd4.w};
            float lv[4];
#pragma unroll
            for (int q = 0; q < 4; q++) {
                float x = si[h] + sdv[q];
                float lr = x > 0.f ? x : ALPHA * x;
                float l = (msk[q] ? lr : NEG_BIG) * wv[q];
                lv[q] = l;
                lmax[h] = fmaxf(lmax[h], l);
            }
            *(float4*)&sl[h * NN + jb] = make_float4(lv[0], lv[1], lv[2], lv[3]);
        }
    }
#pragma unroll
    for (int h = 0; h < H; h++) {
        float v = lmax[h];
#pragma unroll
        for (int off = 16; off > 0; off >>= 1) v = fmaxf(v, __shfl_xor_sync(0xffffffffu, v, off));
        if ((tid & 31) == 0) red[h][tid >> 5] = v;
    }
    __syncthreads();
    if (tid < 8) {
#pragma unroll
        for (int h = 0; h < H; h++) {
            float v = red[h][tid];
#pragma unroll
            for (int off = 4; off > 0; off >>= 1) v = fmaxf(v, __shfl_xor_sync(0xffu, v, off));
            if (tid == 0) red[h][0] = v;
        }
    }
    __syncthreads();
    float rowmax[H];
#pragma unroll
    for (int h = 0; h < H; h++) rowmax[h] = red[h][0];
    __syncthreads();

    float lsum[H];
#pragma unroll
    for (int h = 0; h < H; h++) lsum[h] = 0.f;
    for (int j = tid; j < NN; j += 256) {
#pragma unroll
        for (int h = 0; h < H; h++) {
            float e = __expf(sl[h * NN + j] - rowmax[h]);
            sl[h * NN + j] = e;
            lsum[h] += e;
        }
    }
#pragma unroll
    for (int h = 0; h < H; h++) {
        float v = lsum[h];
#pragma unroll
        for (int off = 16; off > 0; off >>= 1) v += __shfl_xor_sync(0xffffffffu, v, off);
        if ((tid & 31) == 0) red[h][tid >> 5] = v;
    }
    __syncthreads();
    if (tid < 8) {
#pragma unroll
        for (int h = 0; h < H; h++) {
            float v = red[h][tid];
#pragma unroll
            for (int off = 4; off > 0; off >>= 1) v += __shfl_xor_sync(0xffu, v, off);
            if (tid == 0) red[h][0] = v;
        }
    }
    __syncthreads();
    float inv[H];
#pragma unroll
    for (int h = 0; h < H; h++) inv[h] = 1.f / red[h][0];

#pragma unroll
    for (int h = 0; h < H; h++) {
        __half* prow = P + ((long)h * NN + i) * NN;
        const float* slh = sl + h * NN;
        for (int jb = tid * 4; jb < NN; jb += 1024) {
            __half2 h0 = __floats2half2_rn(slh[jb] * inv[h], slh[jb + 1] * inv[h]);
            __half2 h1 = __floats2half2_rn(slh[jb + 2] * inv[h], slh[jb + 3] * inv[h]);
            *(__half2*)(prow + jb) = h0;
            *(__half2*)(prow + jb + 2) = h1;
        }
    }
}
#define ATTN_SMEM (H * NN * 4)

// ---------------- layer-0 epilogue: H1 = elu(LN(elu(Hcat)+R)) -> fp16 ----------------
__global__ __launch_bounds__(256)
void fuse0_kernel(const float* __restrict__ Hcat, const float* __restrict__ R,
                  const float* __restrict__ g, const float* __restrict__ b,
                  __half* __restrict__ H1)
{
    __shared__ float red[8];
    const int n = blockIdx.x;
    const int tid = threadIdx.x;
    float v[8];
    float sum = 0.f;
#pragma unroll
    for (int t = 0; t < 8; t++) {
        int c = tid + t * 256;
        float x = Hcat[(long)n * HCAT + c];
        x = x > 0.f ? x : (expf(x) - 1.f);
        x += R[(long)n * HCAT + c];
        v[t] = x;
        sum += x;
    }
#pragma unroll
    for (int off = 16; off > 0; off >>= 1) sum += __shfl_xor_sync(0xffffffffu, sum, off);
    if ((tid & 31) == 0) red[tid >> 5] = sum;
    __syncthreads();
    if (tid < 8) {
        float x = red[tid];
#pragma unroll
        for (int off = 4; off > 0; off >>= 1) x += __shfl_xor_sync(0xffu, x, off);
        if (tid == 0) red[0] = x;
    }
    __syncthreads();
    const float mean = red[0] / HCAT;
    __syncthreads();
    float vs = 0.f;
#pragma unroll
    for (int t = 0; t < 8; t++) { float d = v[t] - mean; vs += d * d; }
#pragma unroll
    for (int off = 16; off > 0; off >>= 1) vs += __shfl_xor_sync(0xffffffffu, vs, off);
    if ((tid & 31) == 0) red[tid >> 5] = vs;
    __syncthreads();
    if (tid < 8) {
        float x = red[tid];
#pragma unroll
        for (int off = 4; off > 0; off >>= 1) x += __shfl_xor_sync(0xffu, x, off);
        if (tid == 0) red[0] = x;
    }
    __syncthreads();
    const float rstd = rsqrtf(red[0] / HCAT + 1e-5f);
#pragma unroll
    for (int t = 0; t < 8; t++) {
        int c = tid + t * 256;
        float y = (v[t] - mean) * rstd * g[c] + b[c];
        y = y > 0.f ? y : (expf(y) - 1.f);
        H1[(long)n * HCAT + c] = __float2half_rn(y);
    }
}

// ---------------- final: out = LN(sum_h HP1h + R1) ----------------
__global__ __launch_bounds__(256)
void final_kernel(const float* __restrict__ HP1h, const float* __restrict__ R,
                  const float* __restrict__ g, const float* __restrict__ b,
                  float* __restrict__ out)
{
    __shared__ float red[8];
    const int n = blockIdx.x;
    const int tid = threadIdx.x;
    float v[3];
    float sum = 0.f;
#pragma unroll
    for (int t = 0; t < 3; t++) {
        int c = tid + t * 256;
        long off = (long)n * DOUT + c;
        float x = R[off];
#pragma unroll
        for (int h = 0; h < H; h++)
            x += HP1h[(long)h * NN * DOUT + off];
        v[t] = x;
        sum += x;
    }
#pragma unroll
    for (int off = 16; off > 0; off >>= 1) sum += __shfl_xor_sync(0xffffffffu, sum, off);
    if ((tid & 31) == 0) red[tid >> 5] = sum;
    __syncthreads();
    if (tid < 8) {
        float x = red[tid];
#pragma unroll
        for (int off = 4; off > 0; off >>= 1) x += __shfl_xor_sync(0xffu, x, off);
        if (tid == 0) red[0] = x;
    }
    __syncthreads();
    const float mean = red[0] / DOUT;
    __syncthreads();
    float vs = 0.f;
#pragma unroll
    for (int t = 0; t < 3; t++) { float d = v[t] - mean; vs += d * d; }
#pragma unroll
    for (int off = 16; off > 0; off >>= 1) vs += __shfl_xor_sync(0xffffffffu, vs, off);
    if ((tid & 31) == 0) red[tid >> 5] = vs;
    __syncthreads();
    if (tid < 8) {
        float x = red[tid];
#pragma unroll
        for (int off = 4; off > 0; off >>= 1) x += __shfl_xor_sync(0xffu, x, off);
        if (tid == 0) red[0] = x;
    }
    __syncthreads();
    const float rstd = rsqrtf(red[0] / DOUT + 1e-5f);
#pragma unroll
    for (int t = 0; t < 3; t++) {
        int c = tid + t * 256;
        out[(long)n * DOUT + c] = (v[t] - mean) * rstd * g[c] + b[c];
    }
}

// ---------------- host ----------------
extern "C" void kernel_launch(void* const* d_in, const int* in_sizes, int n_in,
                              void* d_out, int out_size)
{
    const float* X    = (const float*)d_in[0];
    const int*   adj  = (const int*)  d_in[1];
    const float* ew   = (const float*)d_in[2];
    const float* W0   = (const float*)d_in[3];
    const float* a0   = (const float*)d_in[4];
    const float* W1   = (const float*)d_in[5];
    const float* a1   = (const float*)d_in[6];
    const float* rp0w = (const float*)d_in[7];
    const float* rp0b = (const float*)d_in[8];
    const float* rp1w = (const float*)d_in[9];
    const float* rp1b = (const float*)d_in[10];
    const float* ln0g = (const float*)d_in[11];
    const float* ln0b = (const float*)d_in[12];
    const float* ln1g = (const float*)d_in[13];
    const float* ln1b = (const float*)d_in[14];
    float* out = (float*)d_out;

    __half *Xh, *W0T, *rp0T, *W1T, *rp1T, *Wh0T, *Wh1T, *P, *H1;
    float *ssrc, *sdst, *Hcat, *R, *HP1h;
    cudaGetSymbolAddress((void**)&Xh,   g_Xh);
    cudaGetSymbolAddress((void**)&W0T,  g_W0T);
    cudaGetSymbolAddress((void**)&rp0T, g_rp0T);
    cudaGetSymbolAddress((void**)&W1T,  g_W1T);
    cudaGetSymbolAddress((void**)&rp1T, g_rp1T);
    cudaGetSymbolAddress((void**)&Wh0T, g_Wh0T);
    cudaGetSymbolAddress((void**)&Wh1T, g_Wh1T);
    cudaGetSymbolAddress((void**)&P,    g_P);
    cudaGetSymbolAddress((void**)&H1,   g_H1);
    cudaGetSymbolAddress((void**)&ssrc, g_ssrc);
    cudaGetSymbolAddress((void**)&sdst, g_sdst);
    cudaGetSymbolAddress((void**)&Hcat, g_Hcat);
    cudaGetSymbolAddress((void**)&R,    g_R);
    cudaGetSymbolAddress((void**)&HP1h, g_HP1h);

    cudaFuncSetAttribute(hgemm_mma, cudaFuncAttributeMaxDynamicSharedMemorySize, GEMM_SMEM);
    cudaFuncSetAttribute(hgemm_dual, cudaFuncAttributeMaxDynamicSharedMemorySize, GEMM_SMEM);
    cudaFuncSetAttribute(attn4_kernel, cudaFuncAttributeMaxDynamicSharedMemorySize, ATTN_SMEM);

    dim3 blk(256);
    dim3 tb(32, 8);

    // ---- prep (launch #4 is hgemm_dual, for ncu visibility) ----
    transpose2<<<dim3(HCAT/32, DIN/32, H + 1), tb>>>(W0, W0T, HID, H, rp0w, rp0T, HCAT, DIN);
    transpose2<<<dim3(DOUT/32, HCAT/32, H + 1), tb>>>(W1, W1T, DOUT, H, rp1w, rp1T, DOUT, HCAT);
    { long n = (long)NN * DIN; conv_half<<<(unsigned)((n/4 + 255)/256), blk>>>(X, Xh, n); }

    // ===== Layer 0 =====
    // Fused: Wh0T[h] = (Xh @ W0[h])^T  AND  R = Xh @ rp0w + rp0b  (both K=768)
    {
        int nx0 = HID / BN;                  // 4
        int nt0 = nx0 * NYT * H;             // 512
        int nx1 = HCAT / BN;                 // 16
        hgemm_dual<<<nt0 + nx1 * NYT, blk, GEMM_SMEM>>>(
            Xh, DIN,
            W0T, Wh0T, (long)HID * DIN, (long)HID * NN, NN, 1.f, nullptr, 1, nx0, nt0,
            rp0T, R, 0L, 0L, HCAT, 1.f, rp0b, 0, nx1);
    }
    scores_kernel<<<dim3(NN/256, H), blk>>>(Wh0T, a0, ssrc, sdst, HID);
    attn4_kernel<<<NN, blk, ATTN_SMEM>>>(adj, ew, ssrc, sdst, P);
    // Hcat[n][h*512+o] = P[h] @ Wh0[h] : N=512 K=4096, f32 store ldc=2048
    hgemm_mma<<<dim3(HID/BN, NN/BM, H), blk, GEMM_SMEM>>>(
        P, Wh0T, Hcat, NN, (long)NN * NN, (long)HID * NN, (long)HID, HCAT,
        1.f, nullptr, 0);
    fuse0_kernel<<<NN, blk>>>(Hcat, R, ln0g, ln0b, H1);

    // ===== Layer 1 =====
    // Fused: Wh1T[h] = (H1 @ W1[h])^T  AND  R1 = H1 @ rp1w + rp1b  (both K=2048)
    {
        int nx0 = DOUT / BN;                 // 6
        int nt0 = nx0 * NYT * H;             // 768
        int nx1 = DOUT / BN;                 // 6
        hgemm_dual<<<nt0 + nx1 * NYT, blk, GEMM_SMEM>>>(
            H1, HCAT,
            W1T, Wh1T, (long)DOUT * HCAT, (long)DOUT * NN, NN, 1.f, nullptr, 1, nx0, nt0,
            rp1T, R, 0L, 0L, DOUT, 1.f, rp1b, 0, nx1);
    }
    scores_kernel<<<dim3(NN/256, H), blk>>>(Wh1T, a1, ssrc, sdst, DOUT);
    attn4_kernel<<<NN, blk, ATTN_SMEM>>>(adj, ew, ssrc, sdst, P);
    // HP1h[h] = 0.25 * P[h] @ Wh1[h] : N=768 K=4096, f32 store
    hgemm_mma<<<dim3(DOUT/BN, NN/BM, H), blk, GEMM_SMEM>>>(
        P, Wh1T, HP1h, NN, (long)NN * NN, (long)DOUT * NN, (long)NN * DOUT, DOUT,
        0.25f, nullptr, 0);
    final_kernel<<<NN, blk>>>(HP1h, R, ln1g, ln1b, out);
}